// round 7
// baseline (speedup 1.0000x reference)
#include <cuda_runtime.h>
#include <cuda_fp16.h>
#include <math.h>

#define NN 50000
#define EE 800000
#define FIN 128
#define HEADS 8
#define HID 32
#define FHID 256          // HEADS*HID
#define CC 40
#define NEG 0.2f

// ---------------- scratch (static device memory; no allocs allowed) --------
__device__ float  g_h1[NN * FHID];        // x@W1 (fp32, for alpha logits)
__device__ __half g_h1h[NN * FHID];       // x@W1 (fp16, for message gather)
__device__ float  g_out1[NN * FHID];      // elu(agg1 + b1)
__device__ float  g_as1[NN * HEADS];
__device__ float  g_ad1[NN * HEADS];
__device__ float  g_h2[NN * CC];          // out1@W2
__device__ float  g_as2[NN];
__device__ float  g_ad2[NN];
__device__ int    g_cnt[NN];              // degree, then scatter cursor
__device__ int    g_rowptr[NN + 1];
__device__ int    g_srci[EE + NN];        // src node per CSR slot (self-loops included)

// ---------------- helpers --------------------------------------------------
__device__ __forceinline__ float wredmax(float v) {
#pragma unroll
    for (int o = 16; o; o >>= 1) v = fmaxf(v, __shfl_xor_sync(0xffffffffu, v, o));
    return v;
}
__device__ __forceinline__ float wredsum(float v) {
#pragma unroll
    for (int o = 16; o; o >>= 1) v += __shfl_xor_sync(0xffffffffu, v, o);
    return v;
}
__device__ __forceinline__ float lrelu(float x) { return x > 0.f ? x : NEG * x; }

// ---------------- CSR build ------------------------------------------------
__global__ void k_init_deg() {
    int v = blockIdx.x * blockDim.x + threadIdx.x;
    if (v < NN) g_cnt[v] = 1;  // self-loop
}

__global__ void k_hist(const int* __restrict__ ei) {
    int e = blockIdx.x * blockDim.x + threadIdx.x;
    if (e < EE) atomicAdd(&g_cnt[ei[EE + e]], 1);
}

// single-block shuffle scan: 49 chunks of 1024, few barriers each
__global__ void k_scan() {
    __shared__ int wsum[32];
    __shared__ int carry_s;
    int tid = threadIdx.x, lane = tid & 31, wid = tid >> 5;
    if (tid == 0) { carry_s = 0; g_rowptr[0] = 0; }
    __syncthreads();
    for (int base = 0; base < NN; base += 1024) {
        int i = base + tid;
        int v = (i < NN) ? g_cnt[i] : 0;
#pragma unroll
        for (int o = 1; o < 32; o <<= 1) {
            int t = __shfl_up_sync(0xffffffffu, v, o);
            if (lane >= o) v += t;
        }
        if (lane == 31) wsum[wid] = v;
        __syncthreads();
        if (wid == 0) {
            int s = wsum[lane];
#pragma unroll
            for (int o = 1; o < 32; o <<= 1) {
                int t = __shfl_up_sync(0xffffffffu, s, o);
                if (lane >= o) s += t;
            }
            wsum[lane] = s;
        }
        __syncthreads();
        int pre = (wid ? wsum[wid - 1] : 0) + carry_s;
        if (i < NN) g_rowptr[i + 1] = pre + v;
        __syncthreads();
        if (tid == 0) carry_s += wsum[31];
        __syncthreads();
    }
}

__global__ void k_selfloop() {
    int v = blockIdx.x * blockDim.x + threadIdx.x;
    if (v < NN) {
        int p = g_rowptr[v];
        g_srci[p] = v;
        g_cnt[v] = p + 1;   // cursor past self-loop
    }
}

__global__ void k_scatter(const int* __restrict__ ei) {
    int e = blockIdx.x * blockDim.x + threadIdx.x;
    if (e < EE) {
        int dst = ei[EE + e];
        int src = ei[e];
        int pos = atomicAdd(&g_cnt[dst], 1);
        g_srci[pos] = src;
    }
}

// ---------------- GEMM1: h1 = x @ W1  (50000x128 @ 128x256) ----------------
// 128x128 tile, 256 threads, 8x8 per thread; epilogue writes fp32 + fp16
__global__ __launch_bounds__(256) void k_gemm1(const float* __restrict__ x,
                                               const float* __restrict__ W) {
    __shared__ float As[128 * 17];
    __shared__ float Bs[16 * 128];
    int tid = threadIdx.x;
    int brow = blockIdx.y * 128, bcol = blockIdx.x * 128;
    int tx = tid & 15, ty = tid >> 4;
    float acc[8][8];
#pragma unroll
    for (int i = 0; i < 8; i++)
#pragma unroll
        for (int j = 0; j < 8; j++) acc[i][j] = 0.f;

    for (int kt = 0; kt < FIN; kt += 16) {
#pragma unroll
        for (int l = 0; l < 2; l++) {
            int idx = tid + l * 256;            // 0..511
            int r = idx >> 2, c = (idx & 3) * 4;
            float4 v = make_float4(0.f, 0.f, 0.f, 0.f);
            int gr = brow + r;
            if (gr < NN) v = *(const float4*)(x + gr * FIN + kt + c);
            As[r * 17 + c + 0] = v.x;
            As[r * 17 + c + 1] = v.y;
            As[r * 17 + c + 2] = v.z;
            As[r * 17 + c + 3] = v.w;
        }
#pragma unroll
        for (int l = 0; l < 2; l++) {
            int idx = tid + l * 256;
            int r = idx >> 5, c = (idx & 31) * 4;
            *(float4*)(Bs + r * 128 + c) = *(const float4*)(W + (kt + r) * FHID + bcol + c);
        }
        __syncthreads();
#pragma unroll
        for (int k = 0; k < 16; k++) {
            float a[8];
#pragma unroll
            for (int i = 0; i < 8; i++) a[i] = As[(ty * 8 + i) * 17 + k];
            float4 b0 = *(float4*)(Bs + k * 128 + tx * 8);
            float4 b1 = *(float4*)(Bs + k * 128 + tx * 8 + 4);
            float b[8] = {b0.x, b0.y, b0.z, b0.w, b1.x, b1.y, b1.z, b1.w};
#pragma unroll
            for (int i = 0; i < 8; i++)
#pragma unroll
                for (int j = 0; j < 8; j++) acc[i][j] += a[i] * b[j];
        }
        __syncthreads();
    }
#pragma unroll
    for (int i = 0; i < 8; i++) {
        int row = brow + ty * 8 + i;
        if (row < NN) {
            float* p = g_h1 + row * FHID + bcol + tx * 8;
            *(float4*)p       = make_float4(acc[i][0], acc[i][1], acc[i][2], acc[i][3]);
            *(float4*)(p + 4) = make_float4(acc[i][4], acc[i][5], acc[i][6], acc[i][7]);
            __half2 h0 = __floats2half2_rn(acc[i][0], acc[i][1]);
            __half2 h1 = __floats2half2_rn(acc[i][2], acc[i][3]);
            __half2 h2 = __floats2half2_rn(acc[i][4], acc[i][5]);
            __half2 h3 = __floats2half2_rn(acc[i][6], acc[i][7]);
            uint4 u;
            u.x = *(unsigned*)&h0; u.y = *(unsigned*)&h1;
            u.z = *(unsigned*)&h2; u.w = *(unsigned*)&h3;
            *(uint4*)(g_h1h + row * FHID + bcol + tx * 8) = u;
        }
    }
}

// ---------------- attention logits, layer 1 --------------------------------
__global__ void k_alpha1(const float* __restrict__ a1s, const float* __restrict__ a1d) {
    int n = blockIdx.x;
    int tid = threadIdx.x;          // tid = head*32 + d  (matches [8,32] layout)
    int head = tid >> 5, d = tid & 31;
    float v = g_h1[n * FHID + tid];
    float ps = wredsum(v * a1s[tid]);
    float pd = wredsum(v * a1d[tid]);
    if (d == 0) {
        g_as1[n * HEADS + head] = ps;
        g_ad1[n * HEADS + head] = pd;
    }
}

// ---------------- layer-1 softmax+agg+ELU: one warp per node ---------------
// lane owns features lane*8..lane*8+7, all in head = lane>>2
__global__ __launch_bounds__(256) void k_agg1w(const float* __restrict__ b1) {
    int w = (blockIdx.x * blockDim.x + threadIdx.x) >> 5;
    if (w >= NN) return;
    int lane = threadIdx.x & 31;
    int head = lane >> 2, sub = lane & 3;
    int beg = g_rowptr[w], deg = g_rowptr[w + 1] - beg;
    float adv = g_ad1[w * HEADS + head];

    // per-head max (4 lanes cooperate per head)
    float mx = -1e30f;
    for (int i = sub; i < deg; i += 4)
        mx = fmaxf(mx, lrelu(g_as1[g_srci[beg + i] * HEADS + head] + adv));
    mx = fmaxf(mx, __shfl_xor_sync(0xffffffffu, mx, 1));
    mx = fmaxf(mx, __shfl_xor_sync(0xffffffffu, mx, 2));
    // per-head sum of exp
    float sm = 0.f;
    for (int i = sub; i < deg; i += 4)
        sm += expf(lrelu(g_as1[g_srci[beg + i] * HEADS + head] + adv) - mx);
    sm += __shfl_xor_sync(0xffffffffu, sm, 1);
    sm += __shfl_xor_sync(0xffffffffu, sm, 2);
    float inv = 1.f / (sm + 1e-16f);

    float acc[8] = {0.f, 0.f, 0.f, 0.f, 0.f, 0.f, 0.f, 0.f};
#pragma unroll 2
    for (int i = 0; i < deg; i++) {
        int s = g_srci[beg + i];
        float wgt = expf(lrelu(g_as1[s * HEADS + head] + adv) - mx) * inv;
        uint4 u = *(const uint4*)(g_h1h + s * FHID + lane * 8);
        float2 f0 = __half22float2(*(__half2*)&u.x);
        float2 f1 = __half22float2(*(__half2*)&u.y);
        float2 f2 = __half22float2(*(__half2*)&u.z);
        float2 f3 = __half22float2(*(__half2*)&u.w);
        acc[0] += wgt * f0.x; acc[1] += wgt * f0.y;
        acc[2] += wgt * f1.x; acc[3] += wgt * f1.y;
        acc[4] += wgt * f2.x; acc[5] += wgt * f2.y;
        acc[6] += wgt * f3.x; acc[7] += wgt * f3.y;
    }
    float* op = g_out1 + w * FHID + lane * 8;
    const float* bp = b1 + lane * 8;
#pragma unroll
    for (int j = 0; j < 8; j++) {
        float r = acc[j] + bp[j];
        op[j] = r > 0.f ? r : expm1f(r);   // ELU
    }
}

// ---------------- GEMM2: h2 = out1 @ W2  (50000x256 @ 256x40) --------------
__global__ void k_gemm2(const float* __restrict__ W2) {
    __shared__ float Ws[FHID * CC];   // 40 KB
    __shared__ float Xs[64 * 17];     // 16-wide k tile, padded
    int tid = threadIdx.x;
    int brow = blockIdx.x * 64;
    for (int i = tid; i < FHID * CC; i += 256) Ws[i] = W2[i];
    int r = tid & 63, cg = tid >> 6;            // 4 col-groups of 10
    int lr = tid >> 2, lc = (tid & 3) * 4;
    float acc[10];
#pragma unroll
    for (int j = 0; j < 10; j++) acc[j] = 0.f;

    for (int kt = 0; kt < FHID; kt += 16) {
        __syncthreads();   // also protects Ws on first iter
        float4 xv = make_float4(0.f, 0.f, 0.f, 0.f);
        int grow = brow + lr;
        if (grow < NN) xv = *(const float4*)(g_out1 + grow * FHID + kt + lc);
        Xs[lr * 17 + lc + 0] = xv.x;
        Xs[lr * 17 + lc + 1] = xv.y;
        Xs[lr * 17 + lc + 2] = xv.z;
        Xs[lr * 17 + lc + 3] = xv.w;
        __syncthreads();
#pragma unroll
        for (int k = 0; k < 16; k++) {
            float x = Xs[r * 17 + k];
            const float* wp = Ws + (kt + k) * CC + cg * 10;
#pragma unroll
            for (int j = 0; j < 10; j++) acc[j] += x * wp[j];
        }
    }
    int row = brow + r;
    if (row < NN) {
#pragma unroll
        for (int j = 0; j < 10; j++) g_h2[row * CC + cg * 10 + j] = acc[j];
    }
}

// ---------------- attention logits, layer 2 --------------------------------
__global__ void k_alpha2(const float* __restrict__ a2s, const float* __restrict__ a2d) {
    int n = blockIdx.x * blockDim.x + threadIdx.x;
    if (n >= NN) return;
    float s = 0.f, d = 0.f;
#pragma unroll
    for (int k = 0; k < CC; k++) {
        float v = g_h2[n * CC + k];
        s += v * a2s[k];
        d += v * a2d[k];
    }
    g_as2[n] = s;
    g_ad2[n] = d;
}

// ---------------- layer-2 softmax+agg: one warp per node -------------------
__global__ __launch_bounds__(256) void k_agg2w(const float* __restrict__ b2,
                                               float* __restrict__ out) {
    int w = (blockIdx.x * blockDim.x + threadIdx.x) >> 5;
    if (w >= NN) return;
    int lane = threadIdx.x & 31;
    int beg = g_rowptr[w], deg = g_rowptr[w + 1] - beg;
    float adv = g_ad2[w];

    float mx = -1e30f;
    for (int i = lane; i < deg; i += 32)
        mx = fmaxf(mx, lrelu(g_as2[g_srci[beg + i]] + adv));
    mx = wredmax(mx);
    float sm = 0.f;
    for (int i = lane; i < deg; i += 32)
        sm += expf(lrelu(g_as2[g_srci[beg + i]] + adv) - mx);
    sm = wredsum(sm);
    float inv = 1.f / (sm + 1e-16f);

    float a0 = 0.f, a1 = 0.f;
#pragma unroll 2
    for (int i = 0; i < deg; i++) {
        int s = g_srci[beg + i];
        float wgt = expf(lrelu(g_as2[s] + adv) - mx) * inv;
        a0 += wgt * g_h2[s * CC + lane];
        if (lane < CC - 32) a1 += wgt * g_h2[s * CC + 32 + lane];
    }
    out[w * CC + lane] = a0 + b2[lane];
    if (lane < CC - 32) out[w * CC + 32 + lane] = a1 + b2[32 + lane];
}

// ---------------- launch ---------------------------------------------------
extern "C" void kernel_launch(void* const* d_in, const int* in_sizes, int n_in,
                              void* d_out, int out_size) {
    const float* x   = (const float*)d_in[0];
    const int*   ei  = (const int*)d_in[1];      // int32 edge_index [2, E]
    const float* W1  = (const float*)d_in[2];
    const float* a1s = (const float*)d_in[3];
    const float* a1d = (const float*)d_in[4];
    const float* b1  = (const float*)d_in[5];
    const float* W2  = (const float*)d_in[6];
    const float* a2s = (const float*)d_in[7];
    const float* a2d = (const float*)d_in[8];
    const float* b2  = (const float*)d_in[9];
    float*       out = (float*)d_out;

    // CSR build (dst-grouped, self-loops first)
    k_init_deg<<<(NN + 255) / 256, 256>>>();
    k_hist<<<(EE + 255) / 256, 256>>>(ei);
    k_scan<<<1, 1024>>>();
    k_selfloop<<<(NN + 255) / 256, 256>>>();
    k_scatter<<<(EE + 255) / 256, 256>>>(ei);

    // layer 1
    dim3 g1(FHID / 128, (NN + 127) / 128);
    k_gemm1<<<g1, 256>>>(x, W1);
    k_alpha1<<<NN, 256>>>(a1s, a1d);
    k_agg1w<<<(NN * 32 + 255) / 256, 256>>>(b1);

    // layer 2
    k_gemm2<<<(NN + 63) / 64, 256>>>(W2);
    k_alpha2<<<(NN + 255) / 256, 256>>>(a2s, a2d);
    k_agg2w<<<(NN * 32 + 255) / 256, 256>>>(b2, out);
}